// round 11
// baseline (speedup 1.0000x reference)
#include <cuda_runtime.h>
#include <cuda_bf16.h>

#define B_SZ 8
#define T_SEQ 2048
#define C_DIM 1024
#define H_DIM 64
#define BT (B_SZ * T_SEQ)

// Scratch (u32-packed bf16x2). q is pre-scaled by 0.125. 16B-aligned for uint4 IO.
__device__ __align__(16) unsigned g_qh[BT * 32], g_ql[BT * 32];
__device__ __align__(16) unsigned g_kh[BT * 32], g_kl[BT * 32];
__device__ __align__(16) unsigned g_vth[B_SZ * 64 * (T_SEQ / 2)], g_vtl[B_SZ * 64 * (T_SEQ / 2)];
__device__ __align__(16) float g_vraw[BT * 64];
__device__ float g_d[BT];   // column softmax denominators (atomic-accumulated)

__device__ __forceinline__ void mma_bf16(float* c, const unsigned* a, const unsigned* b)
{
    asm volatile(
        "mma.sync.aligned.m16n8k16.row.col.f32.bf16.bf16.f32 "
        "{%0,%1,%2,%3}, {%4,%5,%6,%7}, {%8,%9}, {%0,%1,%2,%3};"
        : "+f"(c[0]), "+f"(c[1]), "+f"(c[2]), "+f"(c[3])
        : "r"(a[0]), "r"(a[1]), "r"(a[2]), "r"(a[3]), "r"(b[0]), "r"(b[1]));
}

__device__ __forceinline__ void split2(float x, float y, unsigned& hi, unsigned& lo)
{
    __nv_bfloat16 xh = __float2bfloat16(x);
    __nv_bfloat16 yh = __float2bfloat16(y);
    float xr = x - __bfloat162float(xh);
    float yr = y - __bfloat162float(yh);
    hi = (unsigned)__bfloat16_as_ushort(xh) | ((unsigned)__bfloat16_as_ushort(yh) << 16);
    lo = (unsigned)__bfloat16_as_ushort(__float2bfloat16(xr)) |
         ((unsigned)__bfloat16_as_ushort(__float2bfloat16(yr)) << 16);
}

__global__ void zero_d_kernel()
{
    int i = blockIdx.x * 256 + threadIdx.x;
    if (i < BT) g_d[i] = 0.f;
}

// ---------------------------------------------------------------------------
// Kernel 1: fused QKV projection (R5 structure: inline W split).
// grid = 256 (64-row tiles), block = 256.
// ---------------------------------------------------------------------------
#define PB 18

__global__ __launch_bounds__(256) void qkv_mma(
    const float* __restrict__ x,
    const float* __restrict__ Wq,
    const float* __restrict__ Wk,
    const float* __restrict__ Wv)
{
    __shared__ unsigned xs_h[64 * PB], xs_l[64 * PB];
    __shared__ unsigned ws_h[192 * PB], ws_l[192 * PB];

    const int tid = threadIdx.x, lane = tid & 31, w = tid >> 5;
    const int g = lane >> 2, t4 = lane & 3;
    const int row0 = blockIdx.x * 64;
    const int mrow = 32 * (w & 1);
    const int nf0 = 6 * (w >> 1);

    float acc[2][6][4];
#pragma unroll
    for (int mt = 0; mt < 2; mt++)
#pragma unroll
        for (int nf = 0; nf < 6; nf++)
#pragma unroll
            for (int e = 0; e < 4; e++) acc[mt][nf][e] = 0.f;

    for (int kc = 0; kc < C_DIM; kc += 32) {
        __syncthreads();
#pragma unroll
        for (int i = 0; i < 2; i++) {
            int e = tid * 4 + i * 1024;
            int r = e >> 5, c = e & 31;
            float4 v = *(const float4*)(x + (size_t)(row0 + r) * C_DIM + kc + c);
            unsigned h0, l0, h1, l1;
            split2(v.x, v.y, h0, l0);
            split2(v.z, v.w, h1, l1);
            xs_h[r * PB + (c >> 1)] = h0; xs_h[r * PB + (c >> 1) + 1] = h1;
            xs_l[r * PB + (c >> 1)] = l0; xs_l[r * PB + (c >> 1) + 1] = l1;
        }
#pragma unroll
        for (int i = 0; i < 6; i++) {
            int e = tid * 4 + i * 1024;
            int r = e >> 5, c = e & 31;
            const float* Wp = (r < 64) ? (Wq + (size_t)r * C_DIM)
                            : (r < 128) ? (Wk + (size_t)(r - 64) * C_DIM)
                                        : (Wv + (size_t)(r - 128) * C_DIM);
            float4 v = *(const float4*)(Wp + kc + c);
            unsigned h0, l0, h1, l1;
            split2(v.x, v.y, h0, l0);
            split2(v.z, v.w, h1, l1);
            ws_h[r * PB + (c >> 1)] = h0; ws_h[r * PB + (c >> 1) + 1] = h1;
            ws_l[r * PB + (c >> 1)] = l0; ws_l[r * PB + (c >> 1) + 1] = l1;
        }
        __syncthreads();

#pragma unroll
        for (int ks = 0; ks < 2; ks++) {
            unsigned ah[2][4], al[2][4];
            int cu = 8 * ks + t4;
#pragma unroll
            for (int mt = 0; mt < 2; mt++) {
                int r = mrow + 16 * mt + g;
                ah[mt][0] = xs_h[r * PB + cu];       ah[mt][1] = xs_h[(r + 8) * PB + cu];
                ah[mt][2] = xs_h[r * PB + cu + 4];   ah[mt][3] = xs_h[(r + 8) * PB + cu + 4];
                al[mt][0] = xs_l[r * PB + cu];       al[mt][1] = xs_l[(r + 8) * PB + cu];
                al[mt][2] = xs_l[r * PB + cu + 4];   al[mt][3] = xs_l[(r + 8) * PB + cu + 4];
            }
#pragma unroll
            for (int nf = 0; nf < 6; nf++) {
                int hrow = 8 * (nf0 + nf) + g;
                unsigned bh[2], bl[2];
                bh[0] = ws_h[hrow * PB + cu]; bh[1] = ws_h[hrow * PB + cu + 4];
                bl[0] = ws_l[hrow * PB + cu]; bl[1] = ws_l[hrow * PB + cu + 4];
#pragma unroll
                for (int mt = 0; mt < 2; mt++) {
                    mma_bf16(acc[mt][nf], ah[mt], bh);
                    mma_bf16(acc[mt][nf], ah[mt], bl);
                    mma_bf16(acc[mt][nf], al[mt], bh);
                }
            }
        }
    }

#pragma unroll
    for (int mt = 0; mt < 2; mt++) {
#pragma unroll
        for (int nf = 0; nf < 6; nf++) {
            int col = 8 * (nf0 + nf) + 2 * t4;
            size_t r0g = (size_t)(row0 + mrow + 16 * mt + g);
            float c0 = acc[mt][nf][0], c1 = acc[mt][nf][1];
            float c2 = acc[mt][nf][2], c3 = acc[mt][nf][3];
            if (col < 64) {
                unsigned h, l;
                split2(c0 * 0.125f, c1 * 0.125f, h, l);
                g_qh[r0g * 32 + (col >> 1)] = h; g_ql[r0g * 32 + (col >> 1)] = l;
                split2(c2 * 0.125f, c3 * 0.125f, h, l);
                g_qh[(r0g + 8) * 32 + (col >> 1)] = h; g_ql[(r0g + 8) * 32 + (col >> 1)] = l;
            } else if (col < 128) {
                int kc2 = (col - 64) >> 1;
                unsigned h, l;
                split2(c0, c1, h, l);
                g_kh[r0g * 32 + kc2] = h; g_kl[r0g * 32 + kc2] = l;
                split2(c2, c3, h, l);
                g_kh[(r0g + 8) * 32 + kc2] = h; g_kl[(r0g + 8) * 32 + kc2] = l;
            } else {
                int vc = col - 128;
                *(float2*)&g_vraw[r0g * 64 + vc] = make_float2(c0, c1);
                *(float2*)&g_vraw[(r0g + 8) * 64 + vc] = make_float2(c2, c3);
            }
        }
    }
}

// ---------------------------------------------------------------------------
// Kernel 2: partial column denominators, balanced over (s-tile 64, t-chunk 512).
// grid = (80, B), block = 256. atomicAdd into g_d. uint4 tile fills.
// ---------------------------------------------------------------------------
#define PC 36

__global__ __launch_bounds__(256) void colstats_mma()
{
    __shared__ __align__(16) unsigned ks_h[64 * PC], ks_l[64 * PC];
    __shared__ __align__(16) unsigned qs_h[64 * PC], qs_l[64 * PC];
    __shared__ float red[8][64];

    int j = 0, rem = blockIdx.x;
    for (; j < 32; j++) {
        int cnt = 4 - (j >> 3);
        if (rem < cnt) break;
        rem -= cnt;
    }
    const int c = (j >> 3) + rem;

    const int b = blockIdx.y;
    const int s0 = j * 64;
    const int tid = threadIdx.x, lane = tid & 31, w = tid >> 5;
    const int g = lane >> 2, t4 = lane & 3;
    const int mt = w & 3, nh = w >> 2;

    const unsigned* kh = g_kh + (size_t)b * T_SEQ * 32;
    const unsigned* kl = g_kl + (size_t)b * T_SEQ * 32;
    const unsigned* qh = g_qh + (size_t)b * T_SEQ * 32;
    const unsigned* ql = g_ql + (size_t)b * T_SEQ * 32;

    // K tile fill: 512 uint4 per array, 2 iters of 256 threads
#pragma unroll
    for (int i = 0; i < 2; i++) {
        int idx = tid + 256 * i;
        int r = idx >> 3, c4 = (idx & 7) * 4;
        *(uint4*)&ks_h[r * PC + c4] = *(const uint4*)&kh[(size_t)(s0 + r) * 32 + c4];
        *(uint4*)&ks_l[r * PC + c4] = *(const uint4*)&kl[(size_t)(s0 + r) * 32 + c4];
    }

    float dp[8];
#pragma unroll
    for (int i = 0; i < 8; i++) dp[i] = 0.f;

    const int tt_lo = (j > 8 * c) ? j : 8 * c;
    const int tt_hi = 8 * c + 8;
    for (int tt = tt_lo; tt < tt_hi; tt++) {
        const int t0 = tt * 64;
        __syncthreads();
#pragma unroll
        for (int i = 0; i < 2; i++) {
            int idx = tid + 256 * i;
            int r = idx >> 3, c4 = (idx & 7) * 4;
            *(uint4*)&qs_h[r * PC + c4] = *(const uint4*)&qh[(size_t)(t0 + r) * 32 + c4];
            *(uint4*)&qs_l[r * PC + c4] = *(const uint4*)&ql[(size_t)(t0 + r) * 32 + c4];
        }
        __syncthreads();

        unsigned ah[4][4], al[4][4];
#pragma unroll
        for (int ksi = 0; ksi < 4; ksi++) {
            int r = 16 * mt + g;
            int cu = 8 * ksi + t4;
            ah[ksi][0] = qs_h[r * PC + cu];     ah[ksi][1] = qs_h[(r + 8) * PC + cu];
            ah[ksi][2] = qs_h[r * PC + cu + 4]; ah[ksi][3] = qs_h[(r + 8) * PC + cu + 4];
            al[ksi][0] = qs_l[r * PC + cu];     al[ksi][1] = qs_l[(r + 8) * PC + cu];
            al[ksi][2] = qs_l[r * PC + cu + 4]; al[ksi][3] = qs_l[(r + 8) * PC + cu + 4];
        }

        const bool diag = (tt == j);
#pragma unroll
        for (int nf = 0; nf < 4; nf++) {
            float S[4] = {0.f, 0.f, 0.f, 0.f};
            int srow = 32 * nh + 8 * nf + g;
#pragma unroll
            for (int ksi = 0; ksi < 4; ksi++) {
                unsigned bh[2], bl[2];
                int cu = 8 * ksi + t4;
                bh[0] = ks_h[srow * PC + cu]; bh[1] = ks_h[srow * PC + cu + 4];
                bl[0] = ks_l[srow * PC + cu]; bl[1] = ks_l[srow * PC + cu + 4];
                mma_bf16(S, ah[ksi], bh);
                mma_bf16(S, ah[ksi], bl);
                mma_bf16(S, al[ksi], bh);
            }
            if (!diag) {
                dp[2 * nf]     += __expf(S[0]) + __expf(S[2]);
                dp[2 * nf + 1] += __expf(S[1]) + __expf(S[3]);
            } else {
                int scol = s0 + 32 * nh + 8 * nf + 2 * t4;
                int trow = t0 + 16 * mt + g;
                if (trow >= scol)         dp[2 * nf]     += __expf(S[0]);
                if (trow >= scol + 1)     dp[2 * nf + 1] += __expf(S[1]);
                if (trow + 8 >= scol)     dp[2 * nf]     += __expf(S[2]);
                if (trow + 8 >= scol + 1) dp[2 * nf + 1] += __expf(S[3]);
            }
        }
    }

#pragma unroll
    for (int i = 0; i < 8; i++) {
        dp[i] += __shfl_xor_sync(0xffffffffu, dp[i], 4);
        dp[i] += __shfl_xor_sync(0xffffffffu, dp[i], 8);
        dp[i] += __shfl_xor_sync(0xffffffffu, dp[i], 16);
    }
    if (lane < 4) {
#pragma unroll
        for (int nf = 0; nf < 4; nf++) {
            red[w][32 * nh + 8 * nf + 2 * lane]     = dp[2 * nf];
            red[w][32 * nh + 8 * nf + 2 * lane + 1] = dp[2 * nf + 1];
        }
    }
    __syncthreads();
    if (tid < 64) {
        int base = (tid < 32) ? 0 : 4;
        float d = red[base][tid] + red[base + 1][tid] + red[base + 2][tid] + red[base + 3][tid];
        atomicAdd(&g_d[(size_t)b * T_SEQ + s0 + tid], d);
    }
}

// ---------------------------------------------------------------------------
// Kernel 3: v'[s,h] = v[s,h] / d[s], stored transposed [b][h][s] as hi/lo.
// ---------------------------------------------------------------------------
__global__ __launch_bounds__(256) void vscale_kernel()
{
    __shared__ float tile[64][65];
    __shared__ float inv[64];
    const int b = blockIdx.y;
    const int s0 = blockIdx.x * 64;
    const int tid = threadIdx.x;

    if (tid < 64) inv[tid] = 1.0f / g_d[(size_t)b * T_SEQ + s0 + tid];
    __syncthreads();
    for (int idx = tid; idx < 1024; idx += 256) {
        int s = idx >> 4, h4 = (idx & 15) * 4;
        float4 v = *(const float4*)&g_vraw[((size_t)b * T_SEQ + s0 + s) * 64 + h4];
        float iv = inv[s];
        tile[s][h4] = v.x * iv; tile[s][h4 + 1] = v.y * iv;
        tile[s][h4 + 2] = v.z * iv; tile[s][h4 + 3] = v.w * iv;
    }
    __syncthreads();
    for (int idx = tid; idx < 2048; idx += 256) {
        int h = idx >> 5, sp = idx & 31;
        unsigned hi, lo;
        split2(tile[2 * sp][h], tile[2 * sp + 1][h], hi, lo);
        size_t o = ((size_t)b * 64 + h) * (T_SEQ / 2) + (s0 >> 1) + sp;
        g_vth[o] = hi;
        g_vtl[o] = lo;
    }
}

// ---------------------------------------------------------------------------
// Kernel 4: out partials, balanced over (t-tile 64, s-chunk 256).
// grid = (144, B), block = 128. uint4 tile fills. atomicAdd epilogue.
// ---------------------------------------------------------------------------
__global__ __launch_bounds__(128) void out_mma(float* __restrict__ out)
{
    __shared__ __align__(16) unsigned ks_h[64 * PC], ks_l[64 * PC];
    __shared__ __align__(16) unsigned vs_h[64 * PC], vs_l[64 * PC];

    int i = 0, rem = blockIdx.x;
    for (; i < 32; i++) {
        int cnt = (i >> 2) + 1;
        if (rem < cnt) break;
        rem -= cnt;
    }
    const int c = rem;

    const int b = blockIdx.y;
    const int t0 = 64 * i;
    const int tid = threadIdx.x, lane = tid & 31, w = tid >> 5;
    const int g = lane >> 2, t4 = lane & 3;

    const unsigned* qh = g_qh + (size_t)b * T_SEQ * 32;
    const unsigned* ql = g_ql + (size_t)b * T_SEQ * 32;
    const unsigned* kh = g_kh + (size_t)b * T_SEQ * 32;
    const unsigned* kl = g_kl + (size_t)b * T_SEQ * 32;
    const unsigned* vth = g_vth + (size_t)b * 64 * (T_SEQ / 2);
    const unsigned* vtl = g_vtl + (size_t)b * 64 * (T_SEQ / 2);

    const int trow = t0 + 16 * w + g;

    unsigned aqh[4][4], aql[4][4];
#pragma unroll
    for (int ksi = 0; ksi < 4; ksi++) {
        int cu = 8 * ksi + t4;
        aqh[ksi][0] = qh[(size_t)trow * 32 + cu];
        aqh[ksi][1] = qh[(size_t)(trow + 8) * 32 + cu];
        aqh[ksi][2] = qh[(size_t)trow * 32 + cu + 4];
        aqh[ksi][3] = qh[(size_t)(trow + 8) * 32 + cu + 4];
        aql[ksi][0] = ql[(size_t)trow * 32 + cu];
        aql[ksi][1] = ql[(size_t)(trow + 8) * 32 + cu];
        aql[ksi][2] = ql[(size_t)trow * 32 + cu + 4];
        aql[ksi][3] = ql[(size_t)(trow + 8) * 32 + cu + 4];
    }

    float acc[8][4];
#pragma unroll
    for (int nf = 0; nf < 8; nf++)
#pragma unroll
        for (int e = 0; e < 4; e++) acc[nf][e] = 0.f;

    const int st_lo = 4 * c;
    const int st_hi = (4 * c + 3 < i) ? (4 * c + 3) : i;
    for (int st = st_lo; st <= st_hi; st++) {
        const int s0 = 64 * st;
        __syncthreads();
#pragma unroll
        for (int ii = 0; ii < 4; ii++) {
            int idx = tid + 128 * ii;
            int r = idx >> 3, c4 = (idx & 7) * 4;
            *(uint4*)&ks_h[r * PC + c4] = *(const uint4*)&kh[(size_t)(s0 + r) * 32 + c4];
            *(uint4*)&ks_l[r * PC + c4] = *(const uint4*)&kl[(size_t)(s0 + r) * 32 + c4];
            *(uint4*)&vs_h[r * PC + c4] = *(const uint4*)&vth[(size_t)r * (T_SEQ / 2) + (s0 >> 1) + c4];
            *(uint4*)&vs_l[r * PC + c4] = *(const uint4*)&vtl[(size_t)r * (T_SEQ / 2) + (s0 >> 1) + c4];
        }
        __syncthreads();

        float S[8][4];
#pragma unroll
        for (int nf = 0; nf < 8; nf++) {
#pragma unroll
            for (int e = 0; e < 4; e++) S[nf][e] = 0.f;
            int srow = 8 * nf + g;
#pragma unroll
            for (int ksi = 0; ksi < 4; ksi++) {
                unsigned bh[2], bl[2];
                int cu = 8 * ksi + t4;
                bh[0] = ks_h[srow * PC + cu]; bh[1] = ks_h[srow * PC + cu + 4];
                bl[0] = ks_l[srow * PC + cu]; bl[1] = ks_l[srow * PC + cu + 4];
                mma_bf16(S[nf], aqh[ksi], bh);
                mma_bf16(S[nf], aqh[ksi], bl);
                mma_bf16(S[nf], aql[ksi], bh);
            }
        }

        unsigned ph[4][4], pl[4][4];
        const bool diag = (st == i);
#pragma unroll
        for (int fp = 0; fp < 4; fp++) {
#pragma unroll
            for (int half = 0; half < 2; half++) {
                int nf = 2 * fp + half;
                float p0, p1, p2, p3;
                if (!diag) {
                    p0 = __expf(S[nf][0]);
                    p1 = __expf(S[nf][1]);
                    p2 = __expf(S[nf][2]);
                    p3 = __expf(S[nf][3]);
                } else {
                    int sc = s0 + 8 * nf + 2 * t4;
                    p0 = (sc     <= trow)     ? __expf(S[nf][0]) : 0.f;
                    p1 = (sc + 1 <= trow)     ? __expf(S[nf][1]) : 0.f;
                    p2 = (sc     <= trow + 8) ? __expf(S[nf][2]) : 0.f;
                    p3 = (sc + 1 <= trow + 8) ? __expf(S[nf][3]) : 0.f;
                }
                unsigned h01, l01, h23, l23;
                split2(p0, p1, h01, l01);
                split2(p2, p3, h23, l23);
                ph[fp][2 * half] = h01; ph[fp][2 * half + 1] = h23;
                pl[fp][2 * half] = l01; pl[fp][2 * half + 1] = l23;
            }
        }

#pragma unroll
        for (int nf = 0; nf < 8; nf++) {
            int hrow = 8 * nf + g;
#pragma unroll
            for (int kp = 0; kp < 4; kp++) {
                unsigned bh[2], bl[2];
                int cu = 8 * kp + t4;
                bh[0] = vs_h[hrow * PC + cu]; bh[1] = vs_h[hrow * PC + cu + 4];
                bl[0] = vs_l[hrow * PC + cu]; bl[1] = vs_l[hrow * PC + cu + 4];
                mma_bf16(acc[nf], ph[kp], bh);
                mma_bf16(acc[nf], ph[kp], bl);
                mma_bf16(acc[nf], pl[kp], bh);
            }
        }
    }

#pragma unroll
    for (int nf = 0; nf < 8; nf++) {
        int col = 8 * nf + 2 * t4;
        float* p0 = &out[((size_t)b * T_SEQ + trow) * 64 + col];
        float* p1 = &out[((size_t)b * T_SEQ + trow + 8) * 64 + col];
        atomicAdd(p0,     acc[nf][0]);
        atomicAdd(p0 + 1, acc[nf][1]);
        atomicAdd(p1,     acc[nf][2]);
        atomicAdd(p1 + 1, acc[nf][3]);
    }
}

extern "C" void kernel_launch(void* const* d_in, const int* in_sizes, int n_in,
                              void* d_out, int out_size)
{
    const float* x  = (const float*)d_in[0];
    const float* Wq = (const float*)d_in[1];
    const float* Wk = (const float*)d_in[2];
    const float* Wv = (const float*)d_in[3];
    float* out = (float*)d_out;

    cudaMemsetAsync(d_out, 0, (size_t)out_size * sizeof(float));
    zero_d_kernel<<<64, 256>>>();
    qkv_mma<<<256, 256>>>(x, Wq, Wk, Wv);
    colstats_mma<<<dim3(80, B_SZ), 256>>>();
    vscale_kernel<<<dim3(T_SEQ / 64, B_SZ), 256>>>();
    out_mma<<<dim3(144, B_SZ), 128>>>(out);
}

// round 12
// speedup vs baseline: 1.4312x; 1.4312x over previous
#include <cuda_runtime.h>
#include <cuda_bf16.h>

#define B_SZ 8
#define T_SEQ 2048
#define C_DIM 1024
#define H_DIM 64
#define BT (B_SZ * T_SEQ)

// Scratch (u32-packed bf16x2). q is pre-scaled by 0.125.
__device__ unsigned g_qh[BT * 32], g_ql[BT * 32];
__device__ unsigned g_kh[BT * 32], g_kl[BT * 32];
__device__ unsigned g_vth[B_SZ * 64 * (T_SEQ / 2)], g_vtl[B_SZ * 64 * (T_SEQ / 2)]; // [b][h][s/2]
__device__ float g_vraw[BT * 64];
__device__ float g_d[BT];   // column softmax denominators (atomic-accumulated)

__device__ __forceinline__ void mma_bf16(float* c, const unsigned* a, const unsigned* b)
{
    asm volatile(
        "mma.sync.aligned.m16n8k16.row.col.f32.bf16.bf16.f32 "
        "{%0,%1,%2,%3}, {%4,%5,%6,%7}, {%8,%9}, {%0,%1,%2,%3};"
        : "+f"(c[0]), "+f"(c[1]), "+f"(c[2]), "+f"(c[3])
        : "r"(a[0]), "r"(a[1]), "r"(a[2]), "r"(a[3]), "r"(b[0]), "r"(b[1]));
}

__device__ __forceinline__ void split2(float x, float y, unsigned& hi, unsigned& lo)
{
    __nv_bfloat16 xh = __float2bfloat16(x);
    __nv_bfloat16 yh = __float2bfloat16(y);
    float xr = x - __bfloat162float(xh);
    float yr = y - __bfloat162float(yh);
    hi = (unsigned)__bfloat16_as_ushort(xh) | ((unsigned)__bfloat16_as_ushort(yh) << 16);
    lo = (unsigned)__bfloat16_as_ushort(__float2bfloat16(xr)) |
         ((unsigned)__bfloat16_as_ushort(__float2bfloat16(yr)) << 16);
}

__global__ void zero_d_kernel()
{
    int i = blockIdx.x * 256 + threadIdx.x;
    if (i < BT) g_d[i] = 0.f;
}

// ---------------------------------------------------------------------------
// Kernel 1: fused QKV projection. grid = 256 (64-row tiles), block = 256.
// Warp w: m-group w&1 (32 rows), n-group w>>1 (6 n-frags = 48 of 192 cols).
// ---------------------------------------------------------------------------
#define PB 18

__global__ __launch_bounds__(256) void qkv_mma(
    const float* __restrict__ x,
    const float* __restrict__ Wq,
    const float* __restrict__ Wk,
    const float* __restrict__ Wv)
{
    __shared__ unsigned xs_h[64 * PB], xs_l[64 * PB];
    __shared__ unsigned ws_h[192 * PB], ws_l[192 * PB];

    const int tid = threadIdx.x, lane = tid & 31, w = tid >> 5;
    const int g = lane >> 2, t4 = lane & 3;
    const int row0 = blockIdx.x * 64;
    const int mrow = 32 * (w & 1);
    const int nf0 = 6 * (w >> 1);

    float acc[2][6][4];
#pragma unroll
    for (int mt = 0; mt < 2; mt++)
#pragma unroll
        for (int nf = 0; nf < 6; nf++)
#pragma unroll
            for (int e = 0; e < 4; e++) acc[mt][nf][e] = 0.f;

    for (int kc = 0; kc < C_DIM; kc += 32) {
        __syncthreads();
#pragma unroll
        for (int i = 0; i < 2; i++) {
            int e = tid * 4 + i * 1024;
            int r = e >> 5, c = e & 31;
            float4 v = *(const float4*)(x + (size_t)(row0 + r) * C_DIM + kc + c);
            unsigned h0, l0, h1, l1;
            split2(v.x, v.y, h0, l0);
            split2(v.z, v.w, h1, l1);
            xs_h[r * PB + (c >> 1)] = h0; xs_h[r * PB + (c >> 1) + 1] = h1;
            xs_l[r * PB + (c >> 1)] = l0; xs_l[r * PB + (c >> 1) + 1] = l1;
        }
#pragma unroll
        for (int i = 0; i < 6; i++) {
            int e = tid * 4 + i * 1024;
            int r = e >> 5, c = e & 31;
            const float* Wp = (r < 64) ? (Wq + (size_t)r * C_DIM)
                            : (r < 128) ? (Wk + (size_t)(r - 64) * C_DIM)
                                        : (Wv + (size_t)(r - 128) * C_DIM);
            float4 v = *(const float4*)(Wp + kc + c);
            unsigned h0, l0, h1, l1;
            split2(v.x, v.y, h0, l0);
            split2(v.z, v.w, h1, l1);
            ws_h[r * PB + (c >> 1)] = h0; ws_h[r * PB + (c >> 1) + 1] = h1;
            ws_l[r * PB + (c >> 1)] = l0; ws_l[r * PB + (c >> 1) + 1] = l1;
        }
        __syncthreads();

#pragma unroll
        for (int ks = 0; ks < 2; ks++) {
            unsigned ah[2][4], al[2][4];
            int cu = 8 * ks + t4;
#pragma unroll
            for (int mt = 0; mt < 2; mt++) {
                int r = mrow + 16 * mt + g;
                ah[mt][0] = xs_h[r * PB + cu];       ah[mt][1] = xs_h[(r + 8) * PB + cu];
                ah[mt][2] = xs_h[r * PB + cu + 4];   ah[mt][3] = xs_h[(r + 8) * PB + cu + 4];
                al[mt][0] = xs_l[r * PB + cu];       al[mt][1] = xs_l[(r + 8) * PB + cu];
                al[mt][2] = xs_l[r * PB + cu + 4];   al[mt][3] = xs_l[(r + 8) * PB + cu + 4];
            }
#pragma unroll
            for (int nf = 0; nf < 6; nf++) {
                int hrow = 8 * (nf0 + nf) + g;
                unsigned bh[2], bl[2];
                bh[0] = ws_h[hrow * PB + cu]; bh[1] = ws_h[hrow * PB + cu + 4];
                bl[0] = ws_l[hrow * PB + cu]; bl[1] = ws_l[hrow * PB + cu + 4];
#pragma unroll
                for (int mt = 0; mt < 2; mt++) {
                    mma_bf16(acc[mt][nf], ah[mt], bh);
                    mma_bf16(acc[mt][nf], ah[mt], bl);
                    mma_bf16(acc[mt][nf], al[mt], bh);
                }
            }
        }
    }

    // epilogue: q scaled by 0.125 -> hi/lo; k -> hi/lo; v -> fp32
#pragma unroll
    for (int mt = 0; mt < 2; mt++) {
#pragma unroll
        for (int nf = 0; nf < 6; nf++) {
            int col = 8 * (nf0 + nf) + 2 * t4;
            size_t r0g = (size_t)(row0 + mrow + 16 * mt + g);
            float c0 = acc[mt][nf][0], c1 = acc[mt][nf][1];
            float c2 = acc[mt][nf][2], c3 = acc[mt][nf][3];
            if (col < 64) {
                unsigned h, l;
                split2(c0 * 0.125f, c1 * 0.125f, h, l);
                g_qh[r0g * 32 + (col >> 1)] = h; g_ql[r0g * 32 + (col >> 1)] = l;
                split2(c2 * 0.125f, c3 * 0.125f, h, l);
                g_qh[(r0g + 8) * 32 + (col >> 1)] = h; g_ql[(r0g + 8) * 32 + (col >> 1)] = l;
            } else if (col < 128) {
                int kc2 = (col - 64) >> 1;
                unsigned h, l;
                split2(c0, c1, h, l);
                g_kh[r0g * 32 + kc2] = h; g_kl[r0g * 32 + kc2] = l;
                split2(c2, c3, h, l);
                g_kh[(r0g + 8) * 32 + kc2] = h; g_kl[(r0g + 8) * 32 + kc2] = l;
            } else {
                int vc = col - 128;
                *(float2*)&g_vraw[r0g * 64 + vc] = make_float2(c0, c1);
                *(float2*)&g_vraw[(r0g + 8) * 64 + vc] = make_float2(c2, c3);
            }
        }
    }
}

// ---------------------------------------------------------------------------
// Kernel 2: partial column denominators, balanced over (s-tile 64, t-chunk 512).
// grid = (80, B), block = 256. atomicAdd into g_d.
// ---------------------------------------------------------------------------
#define PC 36

__global__ __launch_bounds__(256) void colstats_mma()
{
    __shared__ unsigned ks_h[64 * PC], ks_l[64 * PC];
    __shared__ unsigned qs_h[64 * PC], qs_l[64 * PC];
    __shared__ float red[8][64];

    // map blockIdx.x -> (j = s-tile, c = t-chunk); valid c in [j>>3, 4)
    int j = 0, rem = blockIdx.x;
    for (; j < 32; j++) {
        int cnt = 4 - (j >> 3);
        if (rem < cnt) break;
        rem -= cnt;
    }
    const int c = (j >> 3) + rem;

    const int b = blockIdx.y;
    const int s0 = j * 64;
    const int tid = threadIdx.x, lane = tid & 31, w = tid >> 5;
    const int g = lane >> 2, t4 = lane & 3;
    const int mt = w & 3, nh = w >> 2;

    const unsigned* kh = g_kh + (size_t)b * T_SEQ * 32;
    const unsigned* kl = g_kl + (size_t)b * T_SEQ * 32;
    const unsigned* qh = g_qh + (size_t)b * T_SEQ * 32;
    const unsigned* ql = g_ql + (size_t)b * T_SEQ * 32;

    for (int idx = tid; idx < 2048; idx += 256) {
        int r = idx >> 5, cc = idx & 31;
        ks_h[r * PC + cc] = kh[(size_t)(s0 + r) * 32 + cc];
        ks_l[r * PC + cc] = kl[(size_t)(s0 + r) * 32 + cc];
    }

    float dp[8];
#pragma unroll
    for (int i = 0; i < 8; i++) dp[i] = 0.f;

    const int tt_lo = (j > 8 * c) ? j : 8 * c;
    const int tt_hi = 8 * c + 8;
    for (int tt = tt_lo; tt < tt_hi; tt++) {
        const int t0 = tt * 64;
        __syncthreads();
        for (int idx = tid; idx < 2048; idx += 256) {
            int r = idx >> 5, cc = idx & 31;
            qs_h[r * PC + cc] = qh[(size_t)(t0 + r) * 32 + cc];
            qs_l[r * PC + cc] = ql[(size_t)(t0 + r) * 32 + cc];
        }
        __syncthreads();

        unsigned ah[4][4], al[4][4];
#pragma unroll
        for (int ksi = 0; ksi < 4; ksi++) {
            int r = 16 * mt + g;
            int cu = 8 * ksi + t4;
            ah[ksi][0] = qs_h[r * PC + cu];     ah[ksi][1] = qs_h[(r + 8) * PC + cu];
            ah[ksi][2] = qs_h[r * PC + cu + 4]; ah[ksi][3] = qs_h[(r + 8) * PC + cu + 4];
            al[ksi][0] = qs_l[r * PC + cu];     al[ksi][1] = qs_l[(r + 8) * PC + cu];
            al[ksi][2] = qs_l[r * PC + cu + 4]; al[ksi][3] = qs_l[(r + 8) * PC + cu + 4];
        }

#pragma unroll
        for (int nf = 0; nf < 4; nf++) {
            float S[4] = {0.f, 0.f, 0.f, 0.f};
            int srow = 32 * nh + 8 * nf + g;
#pragma unroll
            for (int ksi = 0; ksi < 4; ksi++) {
                unsigned bh[2], bl[2];
                int cu = 8 * ksi + t4;
                bh[0] = ks_h[srow * PC + cu]; bh[1] = ks_h[srow * PC + cu + 4];
                bl[0] = ks_l[srow * PC + cu]; bl[1] = ks_l[srow * PC + cu + 4];
                mma_bf16(S, ah[ksi], bh);
                mma_bf16(S, ah[ksi], bl);
                mma_bf16(S, al[ksi], bh);
            }
            int scol = s0 + 32 * nh + 8 * nf + 2 * t4;
            int trow = t0 + 16 * mt + g;
            if (trow >= scol)         dp[2 * nf]     += __expf(S[0]);
            if (trow >= scol + 1)     dp[2 * nf + 1] += __expf(S[1]);
            if (trow + 8 >= scol)     dp[2 * nf]     += __expf(S[2]);
            if (trow + 8 >= scol + 1) dp[2 * nf + 1] += __expf(S[3]);
        }
    }

#pragma unroll
    for (int i = 0; i < 8; i++) {
        dp[i] += __shfl_xor_sync(0xffffffffu, dp[i], 4);
        dp[i] += __shfl_xor_sync(0xffffffffu, dp[i], 8);
        dp[i] += __shfl_xor_sync(0xffffffffu, dp[i], 16);
    }
    if (lane < 4) {
#pragma unroll
        for (int nf = 0; nf < 4; nf++) {
            red[w][32 * nh + 8 * nf + 2 * lane]     = dp[2 * nf];
            red[w][32 * nh + 8 * nf + 2 * lane + 1] = dp[2 * nf + 1];
        }
    }
    __syncthreads();
    if (tid < 64) {
        int base = (tid < 32) ? 0 : 4;
        float d = red[base][tid] + red[base + 1][tid] + red[base + 2][tid] + red[base + 3][tid];
        atomicAdd(&g_d[(size_t)b * T_SEQ + s0 + tid], d);
    }
}

// ---------------------------------------------------------------------------
// Kernel 3: v'[s,h] = v[s,h] / d[s], stored transposed [b][h][s] as hi/lo.
// ---------------------------------------------------------------------------
__global__ __launch_bounds__(256) void vscale_kernel()
{
    __shared__ float tile[64][65];
    __shared__ float inv[64];
    const int b = blockIdx.y;
    const int s0 = blockIdx.x * 64;
    const int tid = threadIdx.x;

    if (tid < 64) inv[tid] = 1.0f / g_d[(size_t)b * T_SEQ + s0 + tid];
    __syncthreads();
    for (int idx = tid; idx < 4096; idx += 256) {
        int s = idx >> 6, h = idx & 63;
        tile[s][h] = g_vraw[((size_t)b * T_SEQ + s0 + s) * 64 + h] * inv[s];
    }
    __syncthreads();
    for (int idx = tid; idx < 2048; idx += 256) {
        int h = idx >> 5, sp = idx & 31;
        unsigned hi, lo;
        split2(tile[2 * sp][h], tile[2 * sp + 1][h], hi, lo);
        size_t o = ((size_t)b * 64 + h) * (T_SEQ / 2) + (s0 >> 1) + sp;
        g_vth[o] = hi;
        g_vtl[o] = lo;
    }
}

// ---------------------------------------------------------------------------
// Kernel 4: out partials, balanced over (t-tile 64, s-chunk 256).
// grid = (144, B), block = 128 (4 warps, one m16 tile each). atomicAdd epilogue.
// ---------------------------------------------------------------------------
__global__ __launch_bounds__(128) void out_mma(float* __restrict__ out)
{
    __shared__ unsigned ks_h[64 * PC], ks_l[64 * PC];
    __shared__ unsigned vs_h[64 * PC], vs_l[64 * PC];

    // map blockIdx.x -> (i = t-tile, c = s-chunk); valid c in [0, (i>>2)+1)
    int i = 0, rem = blockIdx.x;
    for (; i < 32; i++) {
        int cnt = (i >> 2) + 1;
        if (rem < cnt) break;
        rem -= cnt;
    }
    const int c = rem;

    const int b = blockIdx.y;
    const int t0 = 64 * i;
    const int tid = threadIdx.x, lane = tid & 31, w = tid >> 5;
    const int g = lane >> 2, t4 = lane & 3;

    const unsigned* qh = g_qh + (size_t)b * T_SEQ * 32;
    const unsigned* ql = g_ql + (size_t)b * T_SEQ * 32;
    const unsigned* kh = g_kh + (size_t)b * T_SEQ * 32;
    const unsigned* kl = g_kl + (size_t)b * T_SEQ * 32;
    const unsigned* vth = g_vth + (size_t)b * 64 * (T_SEQ / 2);
    const unsigned* vtl = g_vtl + (size_t)b * 64 * (T_SEQ / 2);

    const int trow = t0 + 16 * w + g;

    unsigned aqh[4][4], aql[4][4];
#pragma unroll
    for (int ksi = 0; ksi < 4; ksi++) {
        int cu = 8 * ksi + t4;
        aqh[ksi][0] = qh[(size_t)trow * 32 + cu];
        aqh[ksi][1] = qh[(size_t)(trow + 8) * 32 + cu];
        aqh[ksi][2] = qh[(size_t)trow * 32 + cu + 4];
        aqh[ksi][3] = qh[(size_t)(trow + 8) * 32 + cu + 4];
        aql[ksi][0] = ql[(size_t)trow * 32 + cu];
        aql[ksi][1] = ql[(size_t)(trow + 8) * 32 + cu];
        aql[ksi][2] = ql[(size_t)trow * 32 + cu + 4];
        aql[ksi][3] = ql[(size_t)(trow + 8) * 32 + cu + 4];
    }

    float acc[8][4];
#pragma unroll
    for (int nf = 0; nf < 8; nf++)
#pragma unroll
        for (int e = 0; e < 4; e++) acc[nf][e] = 0.f;

    const int st_lo = 4 * c;
    const int st_hi = (4 * c + 3 < i) ? (4 * c + 3) : i;
    for (int st = st_lo; st <= st_hi; st++) {
        const int s0 = 64 * st;
        __syncthreads();
        for (int idx = tid; idx < 2048; idx += 128) {
            int r = idx >> 5, cc = idx & 31;
            ks_h[r * PC + cc] = kh[(size_t)(s0 + r) * 32 + cc];
            ks_l[r * PC + cc] = kl[(size_t)(s0 + r) * 32 + cc];
            vs_h[r * PC + cc] = vth[(size_t)r * (T_SEQ / 2) + (s0 >> 1) + cc];
            vs_l[r * PC + cc] = vtl[(size_t)r * (T_SEQ / 2) + (s0 >> 1) + cc];
        }
        __syncthreads();

        float S[8][4];
#pragma unroll
        for (int nf = 0; nf < 8; nf++) {
#pragma unroll
            for (int e = 0; e < 4; e++) S[nf][e] = 0.f;
            int srow = 8 * nf + g;
#pragma unroll
            for (int ksi = 0; ksi < 4; ksi++) {
                unsigned bh[2], bl[2];
                int cu = 8 * ksi + t4;
                bh[0] = ks_h[srow * PC + cu]; bh[1] = ks_h[srow * PC + cu + 4];
                bl[0] = ks_l[srow * PC + cu]; bl[1] = ks_l[srow * PC + cu + 4];
                mma_bf16(S[nf], aqh[ksi], bh);
                mma_bf16(S[nf], aqh[ksi], bl);
                mma_bf16(S[nf], aql[ksi], bh);
            }
        }

        unsigned ph[4][4], pl[4][4];
#pragma unroll
        for (int fp = 0; fp < 4; fp++) {
#pragma unroll
            for (int half = 0; half < 2; half++) {
                int nf = 2 * fp + half;
                int sc = s0 + 8 * nf + 2 * t4;
                float p0 = (sc     <= trow)     ? __expf(S[nf][0]) : 0.f;
                float p1 = (sc + 1 <= trow)     ? __expf(S[nf][1]) : 0.f;
                float p2 = (sc     <= trow + 8) ? __expf(S[nf][2]) : 0.f;
                float p3 = (sc + 1 <= trow + 8) ? __expf(S[nf][3]) : 0.f;
                unsigned h01, l01, h23, l23;
                split2(p0, p1, h01, l01);
                split2(p2, p3, h23, l23);
                ph[fp][2 * half] = h01; ph[fp][2 * half + 1] = h23;
                pl[fp][2 * half] = l01; pl[fp][2 * half + 1] = l23;
            }
        }

#pragma unroll
        for (int nf = 0; nf < 8; nf++) {
            int hrow = 8 * nf + g;
#pragma unroll
            for (int kp = 0; kp < 4; kp++) {
                unsigned bh[2], bl[2];
                int cu = 8 * kp + t4;
                bh[0] = vs_h[hrow * PC + cu]; bh[1] = vs_h[hrow * PC + cu + 4];
                bl[0] = vs_l[hrow * PC + cu]; bl[1] = vs_l[hrow * PC + cu + 4];
                mma_bf16(acc[nf], ph[kp], bh);
                mma_bf16(acc[nf], ph[kp], bl);
                mma_bf16(acc[nf], pl[kp], bh);
            }
        }
    }

#pragma unroll
    for (int nf = 0; nf < 8; nf++) {
        int col = 8 * nf + 2 * t4;
        float* p0 = &out[((size_t)b * T_SEQ + trow) * 64 + col];
        float* p1 = &out[((size_t)b * T_SEQ + trow + 8) * 64 + col];
        atomicAdd(p0,     acc[nf][0]);
        atomicAdd(p0 + 1, acc[nf][1]);
        atomicAdd(p1,     acc[nf][2]);
        atomicAdd(p1 + 1, acc[nf][3]);
    }
}

extern "C" void kernel_launch(void* const* d_in, const int* in_sizes, int n_in,
                              void* d_out, int out_size)
{
    const float* x  = (const float*)d_in[0];
    const float* Wq = (const float*)d_in[1];
    const float* Wk = (const float*)d_in[2];
    const float* Wv = (const float*)d_in[3];
    float* out = (float*)d_out;

    cudaMemsetAsync(d_out, 0, (size_t)out_size * sizeof(float));
    zero_d_kernel<<<64, 256>>>();
    qkv_mma<<<dim3(256), 256>>>(x, Wq, Wk, Wv);
    colstats_mma<<<dim3(80, B_SZ), 256>>>();
    vscale_kernel<<<dim3(T_SEQ / 64, B_SZ), 256>>>();
    out_mma<<<dim3(144, B_SZ), 128>>>(out);
}